// round 1
// baseline (speedup 1.0000x reference)
#include <cuda_runtime.h>
#include <cstdint>

// 26 node coordinates (float32, compile-time init -> no runtime copy needed)
__constant__ float2 c_nodes[26] = {
    {0.5454545454545454f, 0.76f}, {0.6022727272727273f, 0.76f},
    {0.5454545454545454f, 0.86f}, {0.6022727272727273f, 0.86f},
    {0.4772727272727273f, 0.76f}, {0.42045454545454547f, 0.76f},
    {0.42045454545454547f, 0.86f}, {0.4772727272727273f, 0.86f},
    {0.32954545454545453f, 0.808f}, {0.42045454545454547f, 0.48f},
    {0.4772727272727273f, 0.48f}, {0.4772727272727273f, 0.38f},
    {0.42045454545454547f, 0.38f}, {0.32954545454545453f, 0.428f},
    {0.5727272727272728f, 0.62f}, {0.7613636363636364f, 0.76f},
    {0.8181818181818182f, 0.76f}, {0.8181818181818182f, 0.86f},
    {0.7613636363636364f, 0.86f}, {0.7909090909090909f, 0.62f},
    {0.9431818181818182f, 0.76f}, {1.0f, 0.76f},
    {1.0f, 0.86f}, {0.9431818181818182f, 0.86f},
    {0.9727272727272728f, 0.62f}, {0.9727272727272728f, 1.0f}
};

// Layout (floats): out[0:6]=x[0:6], out[6:134]=emb[idx1], out[134:138]=x[6:10],
//                  out[138:266]=emb[idx2], out[266:272]=x[10:16]
// In float2 units (136 per row): [0,3)=x2[0..2], [3,67)=e1[0..63],
//                  [67,69)=x2[3..4], [69,133)=e2[0..63], [133,136)=x2[5..7]

__global__ __launch_bounds__(256) void pe_kernel(
    const float* __restrict__ x,
    const float* __restrict__ emb,
    float* __restrict__ out,
    int rows)
{
    int gwarp = (blockIdx.x * blockDim.x + threadIdx.x) >> 5;
    int lane  = threadIdx.x & 31;
    if (gwarp >= rows) return;

    const float* xr = x + (size_t)gwarp * 16;
    // points; same 64B line for all lanes -> L1 broadcast
    float2 pt1 = *reinterpret_cast<const float2*>(xr + 4);
    float2 pt2 = *reinterpret_cast<const float2*>(xr + 8);

    bool m1 = false, m2 = false;
    if (lane < 26) {
        float2 n = c_nodes[lane];
        float tx = 0.01f + 1e-5f * fabsf(n.x);
        float ty = 0.01f + 1e-5f * fabsf(n.y);
        m1 = (fabsf(pt1.x - n.x) <= tx) && (fabsf(pt1.y - n.y) <= ty);
        m2 = (fabsf(pt2.x - n.x) <= tx) && (fabsf(pt2.y - n.y) <= ty);
    }
    unsigned b1 = __ballot_sync(0xffffffffu, m1);
    unsigned b2 = __ballot_sync(0xffffffffu, m2);
    // __ffs is 1-based: node i matched -> idx = i+1; no match -> 0. Exactly the reference.
    int idx1 = __ffs(b1);
    int idx2 = __ffs(b2);

    const float2* e1 = reinterpret_cast<const float2*>(emb + (size_t)idx1 * 128);
    const float2* e2 = reinterpret_cast<const float2*>(emb + (size_t)idx2 * 128);
    const float2* x2 = reinterpret_cast<const float2*>(xr);
    float2* o = reinterpret_cast<float2*>(out + (size_t)gwarp * 272);

    #pragma unroll
    for (int c = lane; c < 136; c += 32) {
        float2 v;
        if (c < 3)        v = x2[c];
        else if (c < 67)  v = e1[c - 3];
        else if (c < 69)  v = x2[c - 64];      // c-67+3
        else if (c < 133) v = e2[c - 69];
        else              v = x2[c - 128];     // c-133+5
        o[c] = v;
    }
}

extern "C" void kernel_launch(void* const* d_in, const int* in_sizes, int n_in,
                              void* d_out, int out_size)
{
    // x has 128*2048*16 = 4194304 elems, emb_table has 100*128 = 12800.
    const float* x;
    const float* emb;
    int xsz;
    if (in_sizes[0] > in_sizes[1]) {
        x = (const float*)d_in[0]; emb = (const float*)d_in[1]; xsz = in_sizes[0];
    } else {
        x = (const float*)d_in[1]; emb = (const float*)d_in[0]; xsz = in_sizes[1];
    }
    int rows = xsz / 16;                 // 262144
    int warps_per_block = 8;             // 256 threads
    int blocks = (rows + warps_per_block - 1) / warps_per_block;
    pe_kernel<<<blocks, 256>>>(x, emb, (float*)d_out, rows);
}